// round 15
// baseline (speedup 1.0000x reference)
#include <cuda_runtime.h>
#include <cuda_bf16.h>
#include <math.h>
#include <stdint.h>
#include <cstdint>

#define NBULK        62
#define DDIM         64
#define NBATCH       8192
#define LOGZ_BLOCKS  4
#define PSI_BLOCKS   256
#define TOTAL_BLOCKS (LOGZ_BLOCKS + PSI_BLOCKS)
#define NTHREADS     256
#define MBLK         32

// ---------------- psi-block shared memory (word/float offsets) ---------------
#define EW         36
#define SM_EHI     0                        // 32*36 = 1152 words (bf16x2 hi)
#define SM_ELO     1152                     // 1152 words
#define SM_RIGHT   2304                     // 128 floats
#define SM_RED     2432                     // 128 floats
#define SM_CFG     2560                     // 512 floats (cfgS[site][m], 2048 B)
#define SM_B       3072                     // byte 12288 (128B aligned); 2 x 8192 u32
#define SM_TOTALF  (3072 + 16384)           // 19456 floats = 77824 bytes -> 2 CTA/SM

// ---------------- global scratch (zero-initialized at load) ------------------
__device__ float    g_bulkT [(size_t)NBULK * 8192];   // bf16 B frags hi|lo (psi + logz ph1)
__device__ float    g_bulkT2[(size_t)NBULK * 8192];   // bf16 B frags hi|lo (logz ph2)
__device__ float    g_envbuf[2][DDIM * DDIM];
__device__ float    g_tmp[128 * 68];
__device__ float    g_maxarr[2][LOGZ_BLOCKS];
__device__ float    g_blocksums[PSI_BLOCKS];
__device__ float    g_logz;
__device__ unsigned g_bar_count;
__device__ volatile unsigned g_bar_gen;
__device__ unsigned g_done;
__device__ unsigned g_fin;

__device__ __forceinline__ void cp16(unsigned dst, const void* src) {
    asm volatile("cp.async.cg.shared.global [%0], [%1], 16;" :: "r"(dst), "l"(src) : "memory");
}
__device__ __forceinline__ void cp_commit() { asm volatile("cp.async.commit_group;" ::: "memory"); }
__device__ __forceinline__ void cp_wait0()  { asm volatile("cp.async.wait_group 0;" ::: "memory"); }
__device__ __forceinline__ void barn(int id) {
    asm volatile("bar.sync %0, 128;" :: "r"(id) : "memory");
}

// m16n8k16 bf16 MMA, f32 accumulate in-place
__device__ __forceinline__ void mma16(float* d, const unsigned* a, unsigned b0, unsigned b1) {
    asm volatile("mma.sync.aligned.m16n8k16.row.col.f32.bf16.bf16.f32 "
                 "{%0,%1,%2,%3}, {%4,%5,%6,%7}, {%8,%9}, {%0,%1,%2,%3};"
                 : "+f"(d[0]), "+f"(d[1]), "+f"(d[2]), "+f"(d[3])
                 : "r"(a[0]), "r"(a[1]), "r"(a[2]), "r"(a[3]), "r"(b0), "r"(b1));
}

__device__ __forceinline__ void split2(float x, float y, unsigned& hi, unsigned& lo) {
    __nv_bfloat162 h = __floats2bfloat162_rn(x, y);
    hi = *reinterpret_cast<unsigned*>(&h);
    float rx = x - __bfloat162float(h.x);
    float ry = y - __bfloat162float(h.y);
    __nv_bfloat162 l = __floats2bfloat162_rn(rx, ry);
    lo = *reinterpret_cast<unsigned*>(&l);
}

// Spin barrier among LOGZ_BLOCKS blocks (thread 0 arrives; caller brackets syncs)
__device__ __forceinline__ void gbar_arrive_spin(unsigned target) {
    __threadfence();
    unsigned t = atomicAdd(&g_bar_count, 1u);
    if (t == LOGZ_BLOCKS - 1) {
        g_bar_count = 0;
        __threadfence();
        g_bar_gen = target;
    } else {
        while (g_bar_gen < target) { }
    }
}

// ============ pre-pass: bake bf16 hi/lo fragment-order operands ==============
__global__ void pre_kernel(const float* __restrict__ bulk) {
    const int t = blockIdx.x;
    const float* src = bulk + (size_t)t * 8192;       // [d][n], n = p*64+j
    unsigned short* d1 = (unsigned short*)(g_bulkT  + (size_t)t * 8192);
    unsigned short* d2 = (unsigned short*)(g_bulkT2 + (size_t)t * 8192);
    for (int idx = threadIdx.x; idx < 8192; idx += blockDim.x) {
        int k = idx >> 7, n = idx & 127;
        float v = src[idx];
        __nv_bfloat16 hb = __float2bfloat16_rn(v);
        __nv_bfloat16 lb = __float2bfloat16_rn(v - __bfloat162float(hb));
        int kt   = k >> 4;
        int lane = ((n & 7) << 2) | ((k >> 1) & 3);
        int b    = (k >> 3) & 1;
        int h2   = k & 1;
        int u32i = ((kt * 16 + (n >> 3)) * 32 + lane) * 2 + b;
        d1[u32i * 2 + h2]        = *reinterpret_cast<unsigned short*>(&hb);
        d1[8192 + u32i * 2 + h2] = *reinterpret_cast<unsigned short*>(&lb);
    }
    for (int idx = threadIdx.x; idx < 8192; idx += blockDim.x) {
        int K = idx >> 6, n = idx & 63;
        float v = src[(K & 63) * 128 + (K >> 6) * 64 + n];
        __nv_bfloat16 hb = __float2bfloat16_rn(v);
        __nv_bfloat16 lb = __float2bfloat16_rn(v - __bfloat162float(hb));
        int kt   = K >> 4;
        int lane = ((n & 7) << 2) | ((K >> 1) & 3);
        int b    = (K >> 3) & 1;
        int h2   = K & 1;
        int u32i = ((kt * 8 + (n >> 3)) * 32 + lane) * 2 + b;
        d2[u32i * 2 + h2]        = *reinterpret_cast<unsigned short*>(&hb);
        d2[8192 + u32i * 2 + h2] = *reinterpret_cast<unsigned short*>(&lb);
    }
}

__global__ __launch_bounds__(NTHREADS, 2)
void main_kernel(const int* __restrict__ cfg,
                 const float* __restrict__ left,
                 const float* __restrict__ bulk,
                 const float* __restrict__ right,
                 float* __restrict__ out) {
    extern __shared__ float smem[];
    const int tid = threadIdx.x;
    const int lane = tid & 31;
    const int w = tid >> 5;
    const int g = lane >> 2, tq = lane & 3;
    const unsigned smem_base = (unsigned)__cvta_generic_to_shared(smem);

    if (blockIdx.x < LOGZ_BLOCKS) {
        // ========= log-Z: 4 cooperating blocks, bf16 MMA, env/tmp via L2 =========
        const int b = blockIdx.x;
        unsigned* maxw = (unsigned*)smem;          // word 0
        float* zpart = smem + 64;                  // 128 floats
        const int mt = w & 3;
        const int ng = w >> 2;                     // 0..1
        const int r0 = mt * 16 + g, r1 = r0 + 8;
        unsigned genl = 0;
        float inv = 1.0f, log_scale = 0.0f;

        if (b == 0) {
            for (int idx = tid; idx < 4096; idx += NTHREADS) {
                int i = idx >> 6, j = idx & 63;
                g_envbuf[0][idx] = left[i] * left[j] + left[64 + i] * left[64 + j];
            }
        }
        __syncthreads();
        if (tid == 0) gbar_arrive_spin(++genl);
        __syncthreads();
        __threadfence();

        for (int t = 0; t < NBULK; t++) {
            const int cur = t & 1, nxt = cur ^ 1;
            const float* envc = g_envbuf[cur];
            const uint2* B1u2 = (const uint2*)(g_bulkT + (size_t)t * 8192);

            // ---- phase1: tmp[d][(p,j)] = env @ [A0|A1]; block covers 4 n-tiles ----
            {
                unsigned ah[4][4], al[4][4];
#pragma unroll
                for (int kt = 0; kt < 4; kt++) {
                    const int c0 = kt * 16 + 2 * tq;
                    float2 x0 = __ldcg((const float2*)&envc[r0 * 64 + c0]);
                    float2 x1 = __ldcg((const float2*)&envc[r1 * 64 + c0]);
                    float2 x2 = __ldcg((const float2*)&envc[r0 * 64 + c0 + 8]);
                    float2 x3 = __ldcg((const float2*)&envc[r1 * 64 + c0 + 8]);
                    split2(x0.x * inv, x0.y * inv, ah[kt][0], al[kt][0]);
                    split2(x1.x * inv, x1.y * inv, ah[kt][1], al[kt][1]);
                    split2(x2.x * inv, x2.y * inv, ah[kt][2], al[kt][2]);
                    split2(x3.x * inv, x3.y * inv, ah[kt][3], al[kt][3]);
                }
                float dh[2][4], dl1[2][4], dl2[2][4];
#pragma unroll
                for (int i = 0; i < 2; i++)
#pragma unroll
                    for (int j = 0; j < 4; j++) { dh[i][j] = 0.f; dl1[i][j] = 0.f; dl2[i][j] = 0.f; }
#pragma unroll
                for (int kt = 0; kt < 4; kt++)
#pragma unroll
                    for (int ntl = 0; ntl < 2; ntl++) {
                        const int ntg = b * 4 + ng * 2 + ntl;
                        uint2 bh = __ldg(B1u2 + (kt * 16 + ntg) * 32 + lane);
                        uint2 bl = __ldg(B1u2 + 2048 + (kt * 16 + ntg) * 32 + lane);
                        mma16(dh[ntl],  ah[kt], bh.x, bh.y);
                        mma16(dl1[ntl], al[kt], bh.x, bh.y);
                        mma16(dl2[ntl], ah[kt], bl.x, bl.y);
                    }
#pragma unroll
                for (int ntl = 0; ntl < 2; ntl++) {
                    const int n0 = (b * 4 + ng * 2 + ntl) * 8 + 2 * tq;
                    g_tmp[(n0    ) * 68 + r0] = dh[ntl][0] + dl1[ntl][0] + dl2[ntl][0];
                    g_tmp[(n0 + 1) * 68 + r0] = dh[ntl][1] + dl1[ntl][1] + dl2[ntl][1];
                    g_tmp[(n0    ) * 68 + r1] = dh[ntl][2] + dl1[ntl][2] + dl2[ntl][2];
                    g_tmp[(n0 + 1) * 68 + r1] = dh[ntl][3] + dl1[ntl][3] + dl2[ntl][3];
                }
            }
            __syncthreads();
            if (tid == 0) { *maxw = 0u; gbar_arrive_spin(++genl); }
            __syncthreads();
            __threadfence();

            // ---- phase2: env'[j][i]; block covers 2 i-tiles ----
            {
                float dh[4], dl1[4], dl2[4];
#pragma unroll
                for (int j = 0; j < 4; j++) { dh[j] = 0.f; dl1[j] = 0.f; dl2[j] = 0.f; }
                const uint2* B2u2 = (const uint2*)(g_bulkT2 + (size_t)t * 8192);
#pragma unroll
                for (int kt2 = 0; kt2 < 8; kt2++) {
                    const int p  = kt2 >> 2;
                    const int d0 = (kt2 & 3) * 16 + 2 * tq;
                    float2 x0 = __ldcg((const float2*)&g_tmp[(p * 64 + r0) * 68 + d0]);
                    float2 x1 = __ldcg((const float2*)&g_tmp[(p * 64 + r1) * 68 + d0]);
                    float2 x2 = __ldcg((const float2*)&g_tmp[(p * 64 + r0) * 68 + d0 + 8]);
                    float2 x3 = __ldcg((const float2*)&g_tmp[(p * 64 + r1) * 68 + d0 + 8]);
                    unsigned ah[4], al[4];
                    split2(x0.x, x0.y, ah[0], al[0]);
                    split2(x1.x, x1.y, ah[1], al[1]);
                    split2(x2.x, x2.y, ah[2], al[2]);
                    split2(x3.x, x3.y, ah[3], al[3]);
                    uint2 bh = __ldg(B2u2 + (kt2 * 8 + b * 2 + ng) * 32 + lane);
                    uint2 bl = __ldg(B2u2 + 2048 + (kt2 * 8 + b * 2 + ng) * 32 + lane);
                    mma16(dh,  ah, bh.x, bh.y);
                    mma16(dl1, al, bh.x, bh.y);
                    mma16(dl2, ah, bl.x, bl.y);
                }
                float ds0 = dh[0] + dl1[0] + dl2[0];
                float ds1 = dh[1] + dl1[1] + dl2[1];
                float ds2 = dh[2] + dl1[2] + dl2[2];
                float ds3 = dh[3] + dl1[3] + dl2[3];
                const int i0 = (b * 2 + ng) * 8 + 2 * tq;
                *(float2*)&g_envbuf[nxt][r0 * 64 + i0] = make_float2(ds0, ds1);
                *(float2*)&g_envbuf[nxt][r1 * 64 + i0] = make_float2(ds2, ds3);
                float am = fmaxf(fmaxf(fabsf(ds0), fabsf(ds1)),
                                 fmaxf(fabsf(ds2), fabsf(ds3)));
#pragma unroll
                for (int off = 16; off > 0; off >>= 1)
                    am = fmaxf(am, __shfl_xor_sync(0xffffffffu, am, off));
                if (lane == 0) atomicMax(maxw, __float_as_uint(am));
            }
            __syncthreads();
            if (tid == 0) {
                g_maxarr[(t & 1) ^ 1][b] = __uint_as_float(*maxw);
                gbar_arrive_spin(++genl);
            }
            __syncthreads();
            __threadfence();

            float mx = 0.0f;
#pragma unroll
            for (int i = 0; i < LOGZ_BLOCKS; i++)
                mx = fmaxf(mx, __ldcg(&g_maxarr[(t & 1) ^ 1][i]));
            float scale = fmaxf(mx, 1e-30f);
            log_scale += logf(scale);
            inv = 1.0f / scale;
        }

        // final env (raw) in g_envbuf[0]; z = sum(right * (env*inv @ right))
        if (b == 0) {
            float part = 0.0f;
            if (tid < 128) {
                int k = tid & 63, pp = tid >> 6;
                float s = 0.0f;
#pragma unroll 8
                for (int e = 0; e < 64; e++)
                    s = fmaf(__ldcg(&g_envbuf[0][k * 64 + e]), right[e * 2 + pp], s);
                part = right[k * 2 + pp] * s;
            }
            if (tid < 128) zpart[tid] = part;
            __syncthreads();
            if (tid == 0) {
                float z = 0.0f;
                for (int i = 0; i < 128; i++) z += zpart[i];
                g_logz = logf(fmaxf(z * inv, 1e-30f)) + log_scale;
                __threadfence();
                unsigned o = atomicAdd(&g_fin, 1u);
                if (o == PSI_BLOCKS) {
                    float s = 0.0f;
                    for (int i = 0; i < PSI_BLOCKS; i++) s += __ldcg(&g_blocksums[i]);
                    out[0] = g_logz - s * (1.0f / (float)NBATCH);
                    __threadfence();
                    g_fin = 0;
                    __threadfence();
                }
            }
        }

        // reset barrier gen for next graph replay
        __syncthreads();
        if (tid == 0) {
            unsigned dn = atomicAdd(&g_done, 1u);
            if (dn == LOGZ_BLOCKS - 1) {
                g_done = 0;
                g_bar_gen = 0;
                __threadfence();
            }
        }
        return;
    }

    // ======= psi: 256 blocks x 32 samples, 256 thr, 2 CTA/SM =================
    const int bi = blockIdx.x - LOGZ_BLOCKS;
    const int m0 = bi * MBLK;
    const int mt = w & 1;           // 2 m-tiles of 16
    const int ng = w >> 1;          // 0..3 (32 n each)
    const int h = ng >> 1;
    const int r0 = mt * 16 + g, r1 = r0 + 8;
    unsigned char* cfgS = (unsigned char*)(smem + SM_CFG);
    unsigned* ehi = (unsigned*)(smem + 0);
    unsigned* elo = (unsigned*)(smem + SM_ELO);
    const unsigned smemB_base = smem_base + SM_B * 4;

    {
        const float4* src = (const float4*)g_bulkT;
#pragma unroll
        for (int i = 0; i < 8; i++)
            cp16(smemB_base + (unsigned)(tid + (i << 8)) * 16u, src + tid + (i << 8));
        cp_commit();
    }

    for (int idx = tid; idx < 64 * MBLK; idx += NTHREADS) {
        int mm = idx & 31, s = idx >> 5;
        cfgS[s * MBLK + mm] = (unsigned char)cfg[(size_t)(m0 + mm) * 64 + s];
    }
    if (tid < 128) smem[SM_RIGHT + tid] = right[tid];
    __syncthreads();

    for (int idx = tid; idx < MBLK * 32; idx += NTHREADS) {
        int mm = idx >> 5, wd = idx & 31;
        const float* lr = left + (int)cfgS[mm] * 64 + 2 * wd;
        unsigned hi, lo;
        split2(lr[0], lr[1], hi, lo);
        ehi[mm * EW + wd] = hi;
        elo[mm * EW + wd] = lo;
    }
    __syncthreads();

    float ps0 = 0.0f, ps1 = 0.0f;

    for (int t = 0; t < NBULK; t++) {
        cp_wait0();
        __syncthreads();

        if (t + 1 < NBULK) {
            const float4* src = (const float4*)(g_bulkT + (size_t)(t + 1) * 8192);
            unsigned dst = smemB_base + (unsigned)(((t + 1) & 1) * 32768u);
#pragma unroll
            for (int i = 0; i < 8; i++)
                cp16(dst + (unsigned)(tid + (i << 8)) * 16u, src + tid + (i << 8));
            cp_commit();
        }

        unsigned ah[4][4], al[4][4];
#pragma unroll
        for (int kt = 0; kt < 4; kt++) {
            const int b0i = r0 * EW + kt * 8 + tq;
            const int b1i = r1 * EW + kt * 8 + tq;
            ah[kt][0] = ehi[b0i];     ah[kt][1] = ehi[b1i];
            ah[kt][2] = ehi[b0i + 4]; ah[kt][3] = ehi[b1i + 4];
            al[kt][0] = elo[b0i];     al[kt][1] = elo[b1i];
            al[kt][2] = elo[b0i + 4]; al[kt][3] = elo[b1i + 4];
        }
        barn(mt + 1);

        const uint2* Bh = (const uint2*)((const unsigned*)(smem + SM_B) + (t & 1) * 8192);
        const uint2* Bl = Bh + 2048;

        float dh[4][4], dl1[4][4], dl2[4][4];
#pragma unroll
        for (int i = 0; i < 4; i++)
#pragma unroll
            for (int j = 0; j < 4; j++) { dh[i][j] = 0.f; dl1[i][j] = 0.f; dl2[i][j] = 0.f; }

#pragma unroll
        for (int kt = 0; kt < 4; kt++)
#pragma unroll
            for (int ntl = 0; ntl < 4; ntl++) {
                uint2 bh = Bh[(kt * 16 + ng * 4 + ntl) * 32 + lane];
                uint2 bl = Bl[(kt * 16 + ng * 4 + ntl) * 32 + lane];
                mma16(dh[ntl],  ah[kt], bh.x, bh.y);
                mma16(dl1[ntl], al[kt], bh.x, bh.y);
                mma16(dl2[ntl], ah[kt], bl.x, bl.y);
            }

        if (t < NBULK - 1) {
            const int sel0 = cfgS[(t + 1) * MBLK + r0];
            const int sel1 = cfgS[(t + 1) * MBLK + r1];
#pragma unroll
            for (int ntl = 0; ntl < 4; ntl++) {
                const int wd = (ng & 1) * 16 + ntl * 4 + tq;
                if (sel0 == h) {
                    unsigned hi, lo;
                    split2(dh[ntl][0] + dl1[ntl][0] + dl2[ntl][0],
                           dh[ntl][1] + dl1[ntl][1] + dl2[ntl][1], hi, lo);
                    ehi[r0 * EW + wd] = hi;
                    elo[r0 * EW + wd] = lo;
                }
                if (sel1 == h) {
                    unsigned hi, lo;
                    split2(dh[ntl][2] + dl1[ntl][2] + dl2[ntl][2],
                           dh[ntl][3] + dl1[ntl][3] + dl2[ntl][3], hi, lo);
                    ehi[r1 * EW + wd] = hi;
                    elo[r1 * EW + wd] = lo;
                }
            }
        } else {
            const int sel0 = cfgS[62 * MBLK + r0], sl0 = cfgS[63 * MBLK + r0];
            const int sel1 = cfgS[62 * MBLK + r1], sl1 = cfgS[63 * MBLK + r1];
#pragma unroll
            for (int ntl = 0; ntl < 4; ntl++) {
                const int j0 = (ng & 1) * 32 + ntl * 8 + 2 * tq;
                if (sel0 == h) {
                    float a = dh[ntl][0] + dl1[ntl][0] + dl2[ntl][0];
                    float bb = dh[ntl][1] + dl1[ntl][1] + dl2[ntl][1];
                    ps0 = fmaf(a, smem[SM_RIGHT + j0 * 2 + sl0], ps0);
                    ps0 = fmaf(bb, smem[SM_RIGHT + (j0 + 1) * 2 + sl0], ps0);
                }
                if (sel1 == h) {
                    float a = dh[ntl][2] + dl1[ntl][2] + dl2[ntl][2];
                    float bb = dh[ntl][3] + dl1[ntl][3] + dl2[ntl][3];
                    ps1 = fmaf(a, smem[SM_RIGHT + j0 * 2 + sl1], ps1);
                    ps1 = fmaf(bb, smem[SM_RIGHT + (j0 + 1) * 2 + sl1], ps1);
                }
            }
        }
    }

    ps0 += __shfl_xor_sync(0xffffffffu, ps0, 1);
    ps0 += __shfl_xor_sync(0xffffffffu, ps0, 2);
    ps1 += __shfl_xor_sync(0xffffffffu, ps1, 1);
    ps1 += __shfl_xor_sync(0xffffffffu, ps1, 2);
    __syncthreads();
    if (tq == 0) {
        smem[SM_RED + ng * 32 + r0] = ps0;
        smem[SM_RED + ng * 32 + r1] = ps1;
    }
    __syncthreads();
    if (tid < 32) {
        float psi = smem[SM_RED + tid] + smem[SM_RED + 32 + tid]
                  + smem[SM_RED + 64 + tid] + smem[SM_RED + 96 + tid];
        smem[SM_RED + tid] = logf(fmaxf(psi * psi, 1e-12f));
    }
    __syncthreads();
    if (tid == 0) {
        float s = 0.0f;
#pragma unroll 8
        for (int i = 0; i < 32; i++) s += smem[SM_RED + i];
        g_blocksums[bi] = s;
        __threadfence();
        unsigned o = atomicAdd(&g_fin, 1u);
        if (o == PSI_BLOCKS) {
            float tot = 0.0f;
            for (int i = 0; i < PSI_BLOCKS; i++) tot += __ldcg(&g_blocksums[i]);
            out[0] = g_logz - tot * (1.0f / (float)NBATCH);
            __threadfence();
            g_fin = 0;
            __threadfence();
        }
    }
}

extern "C" void kernel_launch(void* const* d_in, const int* in_sizes, int n_in,
                              void* d_out, int out_size) {
    const int*   cfg   = (const int*)d_in[0];
    const float* left  = (const float*)d_in[1];
    const float* bulk  = (const float*)d_in[2];
    const float* right = (const float*)d_in[3];

    cudaFuncSetAttribute(main_kernel, cudaFuncAttributeMaxDynamicSharedMemorySize,
                         SM_TOTALF * 4);

    pre_kernel<<<NBULK, 256>>>(bulk);
    main_kernel<<<TOTAL_BLOCKS, NTHREADS, SM_TOTALF * 4>>>(cfg, left, bulk, right,
                                                           (float*)d_out);
}

// round 16
// speedup vs baseline: 2.0724x; 2.0724x over previous
#include <cuda_runtime.h>
#include <cuda_bf16.h>
#include <math.h>
#include <stdint.h>
#include <cstdint>

#define NBULK        62
#define DDIM         64
#define NBATCH       8192
#define PSI_BLOCKS   128
#define TOTAL_BLOCKS (1 + PSI_BLOCKS)
#define NTHREADS     512
#define MBLK         64

// ---------------- psi-block shared memory (word/float offsets) ---------------
#define EW         36
#define SM_EHI     0                        // 64*36 = 2304 words (bf16x2 hi)
#define SM_ELO     2304
#define SM_RIGHT   4608                     // 128 floats
#define SM_RED     4736                     // 256
#define SM_CFG     4992                     // 1024 floats (cfgS[site][m])
#define SM_B       6016                     // byte 24064; 2 x 8192 u32
#define PSI_TOTALF (6016 + 16384)

// ---------------- logz-block shared memory (word offsets) --------------------
#define TW       68                         // tmpT row stride (128 K -> 64 words + pad)
#define LZ_EH    0                          // 64*36 = 2304 words
#define LZ_EL    2304
#define LZ_TH    4608                       // 64*68 = 4352 words (tmpT hi)
#define LZ_TL    8960
#define LZ_ZR    13312                      // 128 floats (z reduce)
#define LZ_B     13440                      // 2 x 16384 words (B1|B2 double buffered)
#define LZ_TOTALF (13440 + 32768)           // 46208 words = 184832 bytes

#define SM_TOTALF LZ_TOTALF

// ---------------- global scratch (zero-initialized at load) ------------------
__device__ float    g_bulkT [(size_t)NBULK * 8192];   // bf16 B frags hi|lo (psi + logz ph1)
__device__ float    g_bulkT2[(size_t)NBULK * 8192];   // bf16 B frags hi|lo (logz ph2)
__device__ float    g_blocksums[PSI_BLOCKS];
__device__ float    g_logz;
__device__ unsigned g_fin;

__device__ __forceinline__ void cp16(unsigned dst, const void* src) {
    asm volatile("cp.async.cg.shared.global [%0], [%1], 16;" :: "r"(dst), "l"(src) : "memory");
}
__device__ __forceinline__ void cp_commit() { asm volatile("cp.async.commit_group;" ::: "memory"); }
__device__ __forceinline__ void cp_wait0()  { asm volatile("cp.async.wait_group 0;" ::: "memory"); }
__device__ __forceinline__ void barn(int id) {
    asm volatile("bar.sync %0, 128;" :: "r"(id) : "memory");
}

// m16n8k16 bf16 MMA, f32 accumulate in-place
__device__ __forceinline__ void mma16(float* d, const unsigned* a, unsigned b0, unsigned b1) {
    asm volatile("mma.sync.aligned.m16n8k16.row.col.f32.bf16.bf16.f32 "
                 "{%0,%1,%2,%3}, {%4,%5,%6,%7}, {%8,%9}, {%0,%1,%2,%3};"
                 : "+f"(d[0]), "+f"(d[1]), "+f"(d[2]), "+f"(d[3])
                 : "r"(a[0]), "r"(a[1]), "r"(a[2]), "r"(a[3]), "r"(b0), "r"(b1));
}

__device__ __forceinline__ void split2(float x, float y, unsigned& hi, unsigned& lo) {
    __nv_bfloat162 h = __floats2bfloat162_rn(x, y);
    hi = *reinterpret_cast<unsigned*>(&h);
    float rx = x - __bfloat162float(h.x);
    float ry = y - __bfloat162float(h.y);
    __nv_bfloat162 l = __floats2bfloat162_rn(rx, ry);
    lo = *reinterpret_cast<unsigned*>(&l);
}
__device__ __forceinline__ void split1(float v, unsigned short& h, unsigned short& l) {
    __nv_bfloat16 hb = __float2bfloat16_rn(v);
    __nv_bfloat16 lb = __float2bfloat16_rn(v - __bfloat162float(hb));
    h = *reinterpret_cast<unsigned short*>(&hb);
    l = *reinterpret_cast<unsigned short*>(&lb);
}

// ============ pre-pass: bake bf16 hi/lo fragment-order operands ==============
__global__ void pre_kernel(const float* __restrict__ bulk) {
    const int t = blockIdx.x;
    const float* src = bulk + (size_t)t * 8192;       // [d][n], n = p*64+j
    unsigned short* d1 = (unsigned short*)(g_bulkT  + (size_t)t * 8192);
    unsigned short* d2 = (unsigned short*)(g_bulkT2 + (size_t)t * 8192);
    for (int idx = threadIdx.x; idx < 8192; idx += blockDim.x) {
        int k = idx >> 7, n = idx & 127;
        float v = src[idx];
        __nv_bfloat16 hb = __float2bfloat16_rn(v);
        __nv_bfloat16 lb = __float2bfloat16_rn(v - __bfloat162float(hb));
        int kt   = k >> 4;
        int lane = ((n & 7) << 2) | ((k >> 1) & 3);
        int b    = (k >> 3) & 1;
        int h2   = k & 1;
        int u32i = ((kt * 16 + (n >> 3)) * 32 + lane) * 2 + b;
        d1[u32i * 2 + h2]        = *reinterpret_cast<unsigned short*>(&hb);
        d1[8192 + u32i * 2 + h2] = *reinterpret_cast<unsigned short*>(&lb);
    }
    for (int idx = threadIdx.x; idx < 8192; idx += blockDim.x) {
        int K = idx >> 6, n = idx & 63;
        float v = src[(K & 63) * 128 + (K >> 6) * 64 + n];
        __nv_bfloat16 hb = __float2bfloat16_rn(v);
        __nv_bfloat16 lb = __float2bfloat16_rn(v - __bfloat162float(hb));
        int kt   = K >> 4;
        int lane = ((n & 7) << 2) | ((K >> 1) & 3);
        int b    = (K >> 3) & 1;
        int h2   = K & 1;
        int u32i = ((kt * 8 + (n >> 3)) * 32 + lane) * 2 + b;
        d2[u32i * 2 + h2]        = *reinterpret_cast<unsigned short*>(&hb);
        d2[8192 + u32i * 2 + h2] = *reinterpret_cast<unsigned short*>(&lb);
    }
}

__global__ __launch_bounds__(NTHREADS, 1)
void main_kernel(const int* __restrict__ cfg,
                 const float* __restrict__ left,
                 const float* __restrict__ bulk,
                 const float* __restrict__ right,
                 float* __restrict__ out) {
    extern __shared__ float smem[];
    const int tid = threadIdx.x;
    const int lane = tid & 31;
    const int w = tid >> 5;
    const int g = lane >> 2, tq = lane & 3;
    const unsigned smem_base = (unsigned)__cvta_generic_to_shared(smem);

    if (blockIdx.x == 0) {
        // ===== log-Z: ONE block, bf16 env-resident, fixed 0.5/site rescale =====
        unsigned* eh = (unsigned*)smem + LZ_EH;
        unsigned* el = (unsigned*)smem + LZ_EL;
        unsigned* th = (unsigned*)smem + LZ_TH;
        unsigned* tl = (unsigned*)smem + LZ_TL;
        unsigned short* ths = (unsigned short*)th;
        unsigned short* tls = (unsigned short*)tl;
        const int mt = w & 3;
        const int ng = w >> 2;          // 0..3
        const int r0 = mt * 16 + g, r1 = r0 + 8;
        const unsigned bufB = smem_base + (unsigned)LZ_B * 4u;

        // env0 = left^T @ left, split to bf16 hi/lo
        for (int idx = tid; idx < 64 * 32; idx += NTHREADS) {
            int i = idx >> 5, wd = idx & 31;
            int j0 = 2 * wd;
            float v0 = left[i] * left[j0] + left[64 + i] * left[64 + j0];
            float v1 = left[i] * left[j0 + 1] + left[64 + i] * left[64 + j0 + 1];
            unsigned hi, lo;
            split2(v0, v1, hi, lo);
            eh[i * EW + wd] = hi;
            el[i * EW + wd] = lo;
        }
        // prefetch B1|B2 for site 0 into buffer 0 (2x 2048 f4 / 512 thr)
        {
            const float4* s1 = (const float4*)g_bulkT;
            const float4* s2 = (const float4*)g_bulkT2;
#pragma unroll
            for (int i = 0; i < 4; i++)
                cp16(bufB + (unsigned)(tid + (i << 9)) * 16u, s1 + tid + (i << 9));
#pragma unroll
            for (int i = 0; i < 4; i++)
                cp16(bufB + 32768u + (unsigned)(tid + (i << 9)) * 16u, s2 + tid + (i << 9));
            cp_commit();
        }

        for (int t = 0; t < NBULK; t++) {
            cp_wait0();
            __syncthreads();            // B(t) resident; env(t) ready

            const unsigned bsel = (unsigned)(t & 1) * 65536u;
            if (t + 1 < NBULK) {
                const unsigned dsel = (unsigned)((t + 1) & 1) * 65536u;
                const float4* s1 = (const float4*)(g_bulkT  + (size_t)(t + 1) * 8192);
                const float4* s2 = (const float4*)(g_bulkT2 + (size_t)(t + 1) * 8192);
#pragma unroll
                for (int i = 0; i < 4; i++)
                    cp16(bufB + dsel + (unsigned)(tid + (i << 9)) * 16u, s1 + tid + (i << 9));
#pragma unroll
                for (int i = 0; i < 4; i++)
                    cp16(bufB + dsel + 32768u + (unsigned)(tid + (i << 9)) * 16u, s2 + tid + (i << 9));
                cp_commit();
            }

            const uint2* B1 = (const uint2*)((unsigned*)smem + LZ_B + (t & 1) * 16384);
            const uint2* B2 = B1 + 4096;

            // ---- phase1: tmp[d][(p,j)] = env @ [A0|A1]; warp: m16 x n32 ----
            {
                unsigned ah[4][4], al[4][4];
#pragma unroll
                for (int kt = 0; kt < 4; kt++) {
                    const int b0i = r0 * EW + kt * 8 + tq;
                    const int b1i = r1 * EW + kt * 8 + tq;
                    ah[kt][0] = eh[b0i];     ah[kt][1] = eh[b1i];
                    ah[kt][2] = eh[b0i + 4]; ah[kt][3] = eh[b1i + 4];
                    al[kt][0] = el[b0i];     al[kt][1] = el[b1i];
                    al[kt][2] = el[b0i + 4]; al[kt][3] = el[b1i + 4];
                }
                float dh[4][4], dl1[4][4], dl2[4][4];
#pragma unroll
                for (int i = 0; i < 4; i++)
#pragma unroll
                    for (int j = 0; j < 4; j++) { dh[i][j] = 0.f; dl1[i][j] = 0.f; dl2[i][j] = 0.f; }
#pragma unroll
                for (int kt = 0; kt < 4; kt++)
#pragma unroll
                    for (int ntl = 0; ntl < 4; ntl++) {
                        uint2 bh = B1[(kt * 16 + ng * 4 + ntl) * 32 + lane];
                        uint2 bl = B1[2048 + (kt * 16 + ng * 4 + ntl) * 32 + lane];
                        mma16(dh[ntl],  ah[kt], bh.x, bh.y);
                        mma16(dl1[ntl], al[kt], bh.x, bh.y);
                        mma16(dl2[ntl], ah[kt], bl.x, bl.y);
                    }
                // store tmpT[j][(p,d)] as bf16 hi/lo halves (transpose in the store)
                const int par0 = r0 & 1;   // r1 = r0+8 -> same parity
#pragma unroll
                for (int ntl = 0; ntl < 4; ntl++) {
                    const int n0 = (ng * 4 + ntl) * 8 + 2 * tq;
                    const int j0 = n0 & 63, p0 = n0 >> 6;
                    const int w0 = p0 * 32 + (r0 >> 1);
                    const int w1 = p0 * 32 + (r1 >> 1);
                    unsigned short h, l;
                    float s;
                    s = dh[ntl][0] + dl1[ntl][0] + dl2[ntl][0];
                    split1(s, h, l);
                    ths[(j0 * TW + w0) * 2 + par0] = h; tls[(j0 * TW + w0) * 2 + par0] = l;
                    s = dh[ntl][1] + dl1[ntl][1] + dl2[ntl][1];
                    split1(s, h, l);
                    ths[((j0 + 1) * TW + w0) * 2 + par0] = h; tls[((j0 + 1) * TW + w0) * 2 + par0] = l;
                    s = dh[ntl][2] + dl1[ntl][2] + dl2[ntl][2];
                    split1(s, h, l);
                    ths[(j0 * TW + w1) * 2 + par0] = h; tls[(j0 * TW + w1) * 2 + par0] = l;
                    s = dh[ntl][3] + dl1[ntl][3] + dl2[ntl][3];
                    split1(s, h, l);
                    ths[((j0 + 1) * TW + w1) * 2 + par0] = h; tls[((j0 + 1) * TW + w1) * 2 + par0] = l;
                }
            }
            __syncthreads();            // tmp ready; env reads done

            // ---- phase2: env'[j][i] = tmpT @ B2, x0.5 rescale; warp: m16 x n16 ----
            {
                float dh[2][4], dl1[2][4], dl2[2][4];
#pragma unroll
                for (int i = 0; i < 2; i++)
#pragma unroll
                    for (int j = 0; j < 4; j++) { dh[i][j] = 0.f; dl1[i][j] = 0.f; dl2[i][j] = 0.f; }
#pragma unroll
                for (int kt2 = 0; kt2 < 8; kt2++) {
                    unsigned a_h[4], a_l[4];
                    const int b0i = r0 * TW + kt2 * 8 + tq;
                    const int b1i = r1 * TW + kt2 * 8 + tq;
                    a_h[0] = th[b0i];     a_h[1] = th[b1i];
                    a_h[2] = th[b0i + 4]; a_h[3] = th[b1i + 4];
                    a_l[0] = tl[b0i];     a_l[1] = tl[b1i];
                    a_l[2] = tl[b0i + 4]; a_l[3] = tl[b1i + 4];
#pragma unroll
                    for (int ntl = 0; ntl < 2; ntl++) {
                        uint2 bh = B2[(kt2 * 8 + ng * 2 + ntl) * 32 + lane];
                        uint2 bl = B2[2048 + (kt2 * 8 + ng * 2 + ntl) * 32 + lane];
                        mma16(dh[ntl],  a_h, bh.x, bh.y);
                        mma16(dl1[ntl], a_l, bh.x, bh.y);
                        mma16(dl2[ntl], a_h, bl.x, bl.y);
                    }
                }
#pragma unroll
                for (int ntl = 0; ntl < 2; ntl++) {
                    const int i0 = (ng * 2 + ntl) * 8 + 2 * tq;
                    const int wd = i0 >> 1;
                    float v0 = (dh[ntl][0] + dl1[ntl][0] + dl2[ntl][0]) * 0.5f;
                    float v1 = (dh[ntl][1] + dl1[ntl][1] + dl2[ntl][1]) * 0.5f;
                    float v2 = (dh[ntl][2] + dl1[ntl][2] + dl2[ntl][2]) * 0.5f;
                    float v3 = (dh[ntl][3] + dl1[ntl][3] + dl2[ntl][3]) * 0.5f;
                    unsigned hi, lo;
                    split2(v0, v1, hi, lo);
                    eh[r0 * EW + wd] = hi; el[r0 * EW + wd] = lo;
                    split2(v2, v3, hi, lo);
                    eh[r1 * EW + wd] = hi; el[r1 * EW + wd] = lo;
                }
            }
            // loop-top __syncthreads publishes env' before next phase1
        }
        __syncthreads();

        // z = sum(right * (env @ right)); logz = log(z) + 62*ln2
        float part = 0.0f;
        if (tid < 128) {
            int k = tid & 63, pp = tid >> 6;
            float s = 0.0f;
#pragma unroll
            for (int wd = 0; wd < 32; wd++) {
                unsigned hw = eh[k * EW + wd], lw = el[k * EW + wd];
                __nv_bfloat162 H = *reinterpret_cast<__nv_bfloat162*>(&hw);
                __nv_bfloat162 L = *reinterpret_cast<__nv_bfloat162*>(&lw);
                float e0 = __bfloat162float(H.x) + __bfloat162float(L.x);
                float e1 = __bfloat162float(H.y) + __bfloat162float(L.y);
                s = fmaf(e0, right[(2 * wd) * 2 + pp], s);
                s = fmaf(e1, right[(2 * wd + 1) * 2 + pp], s);
            }
            part = right[k * 2 + pp] * s;
            smem[LZ_ZR + tid] = part;
        }
        __syncthreads();
        if (tid == 0) {
            float z = 0.0f;
            for (int i = 0; i < 128; i++) z += smem[LZ_ZR + i];
            g_logz = logf(fmaxf(z, 1e-30f)) + 62.0f * 0.69314718055994531f;
            __threadfence();
            unsigned o = atomicAdd(&g_fin, 1u);
            if (o == PSI_BLOCKS) {
                float s = 0.0f;
                for (int i = 0; i < PSI_BLOCKS; i++) s += __ldcg(&g_blocksums[i]);
                out[0] = g_logz - s * (1.0f / (float)NBATCH);
                __threadfence();
                g_fin = 0;
                __threadfence();
            }
        }
        return;
    }

    // ======= psi: 128 blocks x 64 samples, bf16-resident env (R13) ============
    const int bi = blockIdx.x - 1;
    const int m0 = bi * MBLK;
    const int mt = w & 3;
    const int ng = w >> 2;
    const int h = ng >> 1;
    const int r0 = mt * 16 + g, r1 = r0 + 8;
    unsigned char* cfgS = (unsigned char*)(smem + SM_CFG);
    unsigned* ehi = (unsigned*)(smem + SM_EHI);
    unsigned* elo = (unsigned*)(smem + SM_ELO);
    const unsigned smemB_base = smem_base + SM_B * 4;

    {
        const float4* src = (const float4*)g_bulkT;
#pragma unroll
        for (int i = 0; i < 4; i++)
            cp16(smemB_base + (unsigned)(tid + (i << 9)) * 16u, src + tid + (i << 9));
        cp_commit();
    }

    for (int idx = tid; idx < 64 * MBLK; idx += NTHREADS) {
        int mm = idx >> 6, s = idx & 63;
        cfgS[s * MBLK + mm] = (unsigned char)cfg[(size_t)(m0 + mm) * 64 + s];
    }
    if (tid < 128) smem[SM_RIGHT + tid] = right[tid];
    __syncthreads();

    for (int idx = tid; idx < 64 * 32; idx += NTHREADS) {
        int mm = idx >> 5, wd = idx & 31;
        const float* lr = left + (int)cfgS[mm] * 64 + 2 * wd;
        unsigned hi, lo;
        split2(lr[0], lr[1], hi, lo);
        ehi[mm * EW + wd] = hi;
        elo[mm * EW + wd] = lo;
    }
    __syncthreads();

    float ps0 = 0.0f, ps1 = 0.0f;

    for (int t = 0; t < NBULK; t++) {
        cp_wait0();
        __syncthreads();

        if (t + 1 < NBULK) {
            const float4* src = (const float4*)(g_bulkT + (size_t)(t + 1) * 8192);
            unsigned dst = smemB_base + (unsigned)(((t + 1) & 1) * 32768u);
#pragma unroll
            for (int i = 0; i < 4; i++)
                cp16(dst + (unsigned)(tid + (i << 9)) * 16u, src + tid + (i << 9));
            cp_commit();
        }

        unsigned ah[4][4], al[4][4];
#pragma unroll
        for (int kt = 0; kt < 4; kt++) {
            const int b0i = r0 * EW + kt * 8 + tq;
            const int b1i = r1 * EW + kt * 8 + tq;
            ah[kt][0] = ehi[b0i];     ah[kt][1] = ehi[b1i];
            ah[kt][2] = ehi[b0i + 4]; ah[kt][3] = ehi[b1i + 4];
            al[kt][0] = elo[b0i];     al[kt][1] = elo[b1i];
            al[kt][2] = elo[b0i + 4]; al[kt][3] = elo[b1i + 4];
        }
        barn(mt + 1);

        const uint2* Bh = (const uint2*)((const unsigned*)(smem + SM_B) + (t & 1) * 8192);
        const uint2* Bl = Bh + 2048;

        float dh[4][4], dl1[4][4], dl2[4][4];
#pragma unroll
        for (int i = 0; i < 4; i++)
#pragma unroll
            for (int j = 0; j < 4; j++) { dh[i][j] = 0.f; dl1[i][j] = 0.f; dl2[i][j] = 0.f; }

#pragma unroll
        for (int kt = 0; kt < 4; kt++)
#pragma unroll
            for (int ntl = 0; ntl < 4; ntl++) {
                uint2 bh = Bh[(kt * 16 + ng * 4 + ntl) * 32 + lane];
                uint2 bl = Bl[(kt * 16 + ng * 4 + ntl) * 32 + lane];
                mma16(dh[ntl],  ah[kt], bh.x, bh.y);
                mma16(dl1[ntl], al[kt], bh.x, bh.y);
                mma16(dl2[ntl], ah[kt], bl.x, bl.y);
            }

        if (t < NBULK - 1) {
            const int sel0 = cfgS[(t + 1) * MBLK + r0];
            const int sel1 = cfgS[(t + 1) * MBLK + r1];
#pragma unroll
            for (int ntl = 0; ntl < 4; ntl++) {
                const int wd = (ng & 1) * 16 + ntl * 4 + tq;
                if (sel0 == h) {
                    unsigned hi, lo;
                    split2(dh[ntl][0] + dl1[ntl][0] + dl2[ntl][0],
                           dh[ntl][1] + dl1[ntl][1] + dl2[ntl][1], hi, lo);
                    ehi[r0 * EW + wd] = hi;
                    elo[r0 * EW + wd] = lo;
                }
                if (sel1 == h) {
                    unsigned hi, lo;
                    split2(dh[ntl][2] + dl1[ntl][2] + dl2[ntl][2],
                           dh[ntl][3] + dl1[ntl][3] + dl2[ntl][3], hi, lo);
                    ehi[r1 * EW + wd] = hi;
                    elo[r1 * EW + wd] = lo;
                }
            }
        } else {
            const int sel0 = cfgS[62 * MBLK + r0], sl0 = cfgS[63 * MBLK + r0];
            const int sel1 = cfgS[62 * MBLK + r1], sl1 = cfgS[63 * MBLK + r1];
#pragma unroll
            for (int ntl = 0; ntl < 4; ntl++) {
                const int j0 = (ng & 1) * 32 + ntl * 8 + 2 * tq;
                if (sel0 == h) {
                    float a = dh[ntl][0] + dl1[ntl][0] + dl2[ntl][0];
                    float b = dh[ntl][1] + dl1[ntl][1] + dl2[ntl][1];
                    ps0 = fmaf(a, smem[SM_RIGHT + j0 * 2 + sl0], ps0);
                    ps0 = fmaf(b, smem[SM_RIGHT + (j0 + 1) * 2 + sl0], ps0);
                }
                if (sel1 == h) {
                    float a = dh[ntl][2] + dl1[ntl][2] + dl2[ntl][2];
                    float b = dh[ntl][3] + dl1[ntl][3] + dl2[ntl][3];
                    ps1 = fmaf(a, smem[SM_RIGHT + j0 * 2 + sl1], ps1);
                    ps1 = fmaf(b, smem[SM_RIGHT + (j0 + 1) * 2 + sl1], ps1);
                }
            }
        }
    }

    ps0 += __shfl_xor_sync(0xffffffffu, ps0, 1);
    ps0 += __shfl_xor_sync(0xffffffffu, ps0, 2);
    ps1 += __shfl_xor_sync(0xffffffffu, ps1, 1);
    ps1 += __shfl_xor_sync(0xffffffffu, ps1, 2);
    __syncthreads();
    if (tq == 0) {
        smem[SM_RED + ng * 64 + r0] = ps0;
        smem[SM_RED + ng * 64 + r1] = ps1;
    }
    __syncthreads();
    if (tid < 64) {
        float psi = smem[SM_RED + tid] + smem[SM_RED + 64 + tid]
                  + smem[SM_RED + 128 + tid] + smem[SM_RED + 192 + tid];
        smem[SM_RED + tid] = logf(fmaxf(psi * psi, 1e-12f));
    }
    __syncthreads();
    if (tid == 0) {
        float s = 0.0f;
#pragma unroll 8
        for (int i = 0; i < 64; i++) s += smem[SM_RED + i];
        g_blocksums[bi] = s;
        __threadfence();
        unsigned o = atomicAdd(&g_fin, 1u);
        if (o == PSI_BLOCKS) {
            float tot = 0.0f;
            for (int i = 0; i < PSI_BLOCKS; i++) tot += __ldcg(&g_blocksums[i]);
            out[0] = g_logz - tot * (1.0f / (float)NBATCH);
            __threadfence();
            g_fin = 0;
            __threadfence();
        }
    }
}

extern "C" void kernel_launch(void* const* d_in, const int* in_sizes, int n_in,
                              void* d_out, int out_size) {
    const int*   cfg   = (const int*)d_in[0];
    const float* left  = (const float*)d_in[1];
    const float* bulk  = (const float*)d_in[2];
    const float* right = (const float*)d_in[3];

    cudaFuncSetAttribute(main_kernel, cudaFuncAttributeMaxDynamicSharedMemorySize,
                         SM_TOTALF * 4);

    pre_kernel<<<NBULK, 256>>>(bulk);
    main_kernel<<<TOTAL_BLOCKS, NTHREADS, SM_TOTALF * 4>>>(cfg, left, bulk, right,
                                                           (float*)d_out);
}